// round 17
// baseline (speedup 1.0000x reference)
#include <cuda_runtime.h>
#include <math.h>

// Shapes (fixed by the problem)
#define B_   2
#define H_   8
#define N_   64
#define TD_  1024          // T*D = 32*32
#define BH_  (B_ * H_)     // 16
#define INV_SCALE_ (1.0f / 32.0f)   // 1/sqrt(T*D)

#define KCH_  128                // k-elements per chunk (2 x 64 sub-chunks)
#define NCH_  (TD_ / KCH_)       // 8 chunks
#define KSUB_ 64                 // sub-chunk width held in smem
#define SSTR_ 65                 // smem row stride (odd -> conflict-free)

#define NROWS_    (BH_ * N_)     // 1024 output rows
#define PERSIST_  592            // 4 CTAs/SM x 148 SMs (exact single wave)

// Partial scores, row-major: [chunk][bh][i][j].  8*16*64*64 floats = 2 MB
__device__ float g_part[NCH_ * BH_ * N_ * N_];

// ---------------------------------------------------------------------------
// Kernel A (R13 config): partial QK^T. grid = 128 blocks, 256 threads.
// 64x64 score tile over a 128-wide k chunk (two 64-wide sub-chunks through
// the same smem tiles), 4x4 register blocking, coalesced restaged stores.
// ---------------------------------------------------------------------------
__global__ __launch_bounds__(256, 2)
void qk_part_kernel(const float* __restrict__ Q,
                    const float* __restrict__ K)
{
#if __CUDA_ARCH__ >= 900
    cudaTriggerProgrammaticLaunchCompletion();
#endif

    __shared__ float sQ[N_ * SSTR_];
    __shared__ float sK[N_ * SSTR_];

    const int bx = blockIdx.x;           // 0..127
    const int bh = bx & (BH_ - 1);
    const int c  = bx >> 4;              // chunk index 0..7
    const int tid = threadIdx.x;

    const int ty = tid & 15;             // row group
    const int tx = tid >> 4;             // col group

    float acc[4][4];
#pragma unroll
    for (int m = 0; m < 4; ++m)
#pragma unroll
        for (int n = 0; n < 4; ++n) acc[m][n] = 0.0f;

#pragma unroll
    for (int sub = 0; sub < KCH_ / KSUB_; ++sub) {
        const int k0 = c * KCH_ + sub * KSUB_;

#pragma unroll
        for (int it = 0; it < 16; ++it) {
            int idx = tid + 256 * it;
            int row = idx >> 6;
            int col = idx & 63;
            size_t g = (size_t)(bh * N_ + row) * TD_ + k0 + col;
            sQ[row * SSTR_ + col] = Q[g];
            sK[row * SSTR_ + col] = K[g];
        }
        __syncthreads();

#pragma unroll 4
        for (int k = 0; k < KSUB_; ++k) {
            float q[4], kk[4];
#pragma unroll
            for (int m = 0; m < 4; ++m) q[m]  = sQ[(ty + 16 * m) * SSTR_ + k];
#pragma unroll
            for (int n = 0; n < 4; ++n) kk[n] = sK[(tx + 16 * n) * SSTR_ + k];
#pragma unroll
            for (int m = 0; m < 4; ++m)
#pragma unroll
                for (int n = 0; n < 4; ++n)
                    acc[m][n] += q[m] * kk[n];
        }
        __syncthreads();
    }

    // Restage through smem (reuse sQ) so the global store is coalesced.
#pragma unroll
    for (int m = 0; m < 4; ++m)
#pragma unroll
        for (int n = 0; n < 4; ++n)
            sQ[(ty + 16 * m) * SSTR_ + (tx + 16 * n)] = acc[m][n];
    __syncthreads();

    float* dst = g_part + ((size_t)c * BH_ + bh) * (N_ * N_);
#pragma unroll
    for (int it = 0; it < 16; ++it) {
        int idx = tid + 256 * it;
        int row = idx >> 6;
        int col = idx & 63;
        dst[idx] = sQ[row * SSTR_ + col];
    }
}

// ---------------------------------------------------------------------------
// Softmax helper: warp 0 fills s_attn[64] for output row `row`.
// Caller must __syncthreads() after.
// ---------------------------------------------------------------------------
__device__ __forceinline__
void softmax_row(int row, int lane, const int* __restrict__ mask,
                 float* __restrict__ s_attn)
{
    const int i  = row % N_;
    const int bh = row / N_;
    const size_t roff = ((size_t)bh * N_ + i) * N_;
    int m0 = mask[roff + lane];
    int m1 = mask[roff + lane + 32];

    const float* base = g_part + ((size_t)bh * N_ + i) * N_;
    float v0 = 0.0f, v1 = 0.0f;
#pragma unroll
    for (int cch = 0; cch < NCH_; ++cch) {
        const float* p = base + (size_t)cch * (BH_ * N_ * N_);
        v0 += p[lane];
        v1 += p[lane + 32];
    }
    v0 *= INV_SCALE_;
    v1 *= INV_SCALE_;

    if (m0 == 0) v0 = -INFINITY;
    if (m1 == 0) v1 = -INFINITY;

    float mx = fmaxf(v0, v1);
#pragma unroll
    for (int o = 16; o > 0; o >>= 1) mx = fmaxf(mx, __shfl_xor_sync(0xffffffffu, mx, o));
    float e0 = __expf(v0 - mx);
    float e1 = __expf(v1 - mx);
    float s = e0 + e1;
#pragma unroll
    for (int o = 16; o > 0; o >>= 1) s += __shfl_xor_sync(0xffffffffu, s, o);
    float inv = 1.0f / s;
    s_attn[lane]      = e0 * inv;
    s_attn[lane + 32] = e1 * inv;
}

// ---------------------------------------------------------------------------
// Kernel B: persistent, exact single wave. grid = 592 CTAs, 256 threads,
// occ 4. CTA bx handles row bx, then row bx+592 (if any). Row-2's first V
// batch is issued before row-1's store/softmax-2 so the inter-row prologue
// is covered by in-flight loads. PDL overlaps the row-1 prologue with A.
// ---------------------------------------------------------------------------
__global__ __launch_bounds__(256, 4)
void attn_v_kernel(const float* __restrict__ V,
                   const int*   __restrict__ mask,
                   float*       __restrict__ out)
{
    const int bx   = blockIdx.x;          // 0 .. 591
    const int tid  = threadIdx.x;
    const int lane = tid & 31;
    const int warp = tid >> 5;

    __shared__ float s_attn[N_];

    const size_t jstride = (size_t)N_ * (TD_ / 4);   // float4 stride between j's

    const int row0 = bx;
    const int row1 = bx + PERSIST_;                  // valid iff < NROWS_
    const bool has2 = (row1 < NROWS_);

    const int i0 = row0 % N_, bh0 = row0 / N_;
    const float4* V0 = reinterpret_cast<const float4*>(V) +
                       ((size_t)bh0 * N_ * N_ + i0) * (TD_ / 4) + tid;

    // ---- Pre-sync (independent of kernel A's output) ----
    // Demand-load row0's first 8-row V batch; prefetch rows 8..23 to L2.
    float4 v[8];
#pragma unroll
    for (int jj = 0; jj < 8; ++jj)
        v[jj] = __ldcs(&V0[(size_t)jj * jstride]);
#pragma unroll
    for (int j = 8; j < 24; ++j)
        asm volatile("prefetch.global.L2 [%0];" :: "l"(V0 + (size_t)j * jstride));

    // ---- Wait for kernel A's g_part to be visible ----
#if __CUDA_ARCH__ >= 900
    cudaGridDependencySynchronize();
#endif

    // ================= Row 0 =================
    if (warp == 0) softmax_row(row0, lane, mask, s_attn);
    __syncthreads();

    float4 acc = make_float4(0.f, 0.f, 0.f, 0.f);
#pragma unroll
    for (int j0 = 0; j0 < N_; j0 += 8) {
#pragma unroll
        for (int jj = 0; jj < 8; ++jj) {
            float a = s_attn[j0 + jj];
            acc.x += a * v[jj].x;
            acc.y += a * v[jj].y;
            acc.z += a * v[jj].z;
            acc.w += a * v[jj].w;
        }
        if (j0 + 8 < N_) {
#pragma unroll
            for (int jj = 0; jj < 8; ++jj)
                v[jj] = __ldcs(&V0[(size_t)(j0 + 8 + jj) * jstride]);
        }
    }

    // Issue row1's first V batch BEFORE storing row0 / softmax row1,
    // so the inter-row prologue is covered by in-flight DRAM loads.
    const int i1 = row1 % N_, bh1 = row1 / N_;
    const float4* V1 = reinterpret_cast<const float4*>(V) +
                       ((size_t)bh1 * N_ * N_ + i1) * (TD_ / 4) + tid;
    float4 w[8];
    if (has2) {
#pragma unroll
        for (int jj = 0; jj < 8; ++jj)
            w[jj] = __ldcs(&V1[(size_t)jj * jstride]);
    }

    {
        float4* Orow = reinterpret_cast<float4*>(out + (size_t)row0 * TD_);
        __stcs(&Orow[tid], acc);
    }

    if (!has2) return;

    // ================= Row 1 =================
    __syncthreads();                      // all done reading s_attn (row0)
    if (warp == 0) softmax_row(row1, lane, mask, s_attn);
    __syncthreads();

    acc = make_float4(0.f, 0.f, 0.f, 0.f);
#pragma unroll
    for (int j0 = 0; j0 < N_; j0 += 8) {
#pragma unroll
        for (int jj = 0; jj < 8; ++jj) {
            float a = s_attn[j0 + jj];
            acc.x += a * w[jj].x;
            acc.y += a * w[jj].y;
            acc.z += a * w[jj].z;
            acc.w += a * w[jj].w;
        }
        if (j0 + 8 < N_) {
#pragma unroll
            for (int jj = 0; jj < 8; ++jj)
                w[jj] = __ldcs(&V1[(size_t)(j0 + 8 + jj) * jstride]);
        }
    }

    float4* Orow = reinterpret_cast<float4*>(out + (size_t)row1 * TD_);
    __stcs(&Orow[tid], acc);
}

extern "C" void kernel_launch(void* const* d_in, const int* in_sizes, int n_in,
                              void* d_out, int out_size)
{
    const float* Q    = (const float*)d_in[0];
    const float* K    = (const float*)d_in[1];
    const float* V    = (const float*)d_in[2];
    const int*   mask = (const int*)d_in[3];
    float*       out  = (float*)d_out;

    // Kernel A: normal launch
    qk_part_kernel<<<NCH_ * BH_, 256>>>(Q, K);

    // Kernel B: programmatic dependent launch (overlaps prologue with A)
    cudaLaunchConfig_t cfg = {};
    cfg.gridDim  = dim3(PERSIST_);
    cfg.blockDim = dim3(256);
    cfg.dynamicSmemBytes = 0;
    cudaLaunchAttribute attrs[1];
    attrs[0].id = cudaLaunchAttributeProgrammaticStreamSerialization;
    attrs[0].val.programmaticStreamSerializationAllowed = 1;
    cfg.attrs = attrs;
    cfg.numAttrs = 1;
    cudaLaunchKernelEx(&cfg, attn_v_kernel, V, mask, out);
}